// round 1
// baseline (speedup 1.0000x reference)
#include <cuda_runtime.h>

// ---------------------------------------------------------------------------
// Sparse UNet block. All scratch as __device__ globals (no allocation).
// N = 200000 fine voxels (fixed per problem), M <= N coarse voxels (runtime).
// ---------------------------------------------------------------------------

#define NMAX 200704
#define STATS_BLOCKS 256

__device__ float g_part[STATS_BLOCKS * 128];    // [block][2*64] partial sums
__device__ float g_scale[64];
__device__ float g_shift[64];
__device__ float g_cat[(size_t)NMAX * 64];      // [N][64]: skip (0:32) || upsampled (32:64)
__device__ float g_c1[(size_t)NMAX * 64];       // [M][64] down-conv out
__device__ float g_c2[(size_t)NMAX * 64];       // [M][64] coarse submanifold conv out

// ---------------------------------------------------------------------------
// Deterministic batch-stat reduction: fixed-order partials, fixed-order final.
// ---------------------------------------------------------------------------
__global__ void stats_partial(const float* __restrict__ x, int n, int C, int ld) {
    __shared__ float sm[512];
    const int tid = threadIdx.x;
    const int c = tid % C;
    const int rg = tid / C;
    const int RPI = blockDim.x / C;
    float s = 0.f, s2 = 0.f;
    for (int r = blockIdx.x * RPI + rg; r < n; r += gridDim.x * RPI) {
        float v = x[(size_t)r * ld + c];
        s += v;
        s2 += v * v;
    }
    sm[tid] = s;
    sm[256 + tid] = s2;
    __syncthreads();
    if (rg == 0) {
        float ts = 0.f, t2 = 0.f;
        for (int j = 0; j < RPI; j++) { ts += sm[j * C + c]; t2 += sm[256 + j * C + c]; }
        g_part[blockIdx.x * 128 + c] = ts;
        g_part[blockIdx.x * 128 + 64 + c] = t2;
    }
}

__global__ void stats_final(int n, int C, const float* __restrict__ gg, const float* __restrict__ bb) {
    int c = threadIdx.x;
    if (c >= C) return;
    float s = 0.f, s2 = 0.f;
    for (int b = 0; b < STATS_BLOCKS; b++) {
        s += g_part[b * 128 + c];
        s2 += g_part[b * 128 + 64 + c];
    }
    float inv_n = 1.f / (float)n;
    float mu = s * inv_n;
    float var = s2 * inv_n - mu * mu;
    float sc = gg[c] * rsqrtf(var + 1e-4f);
    g_scale[c] = sc;
    g_shift[c] = bb[c] - mu * sc;
}

// ---------------------------------------------------------------------------
// Sparse gather-conv: out[r] = sum_{k : nbr[k][r] < P} bnrelu(in[nbr[k][r]]) @ W[k]
// BN(scale/shift from g_scale/g_shift) + ReLU applied on the fly; sentinel
// rows (== P) are skipped (they contribute exactly zero, matching fpad).
// Weights staged in smem in groups of GT taps; accumulators live in registers
// across groups. Lanes own output channels (1 for Cout=32, float2 for Cout=64).
// Tap skip via ballot over lane-parallel index loads.
// ---------------------------------------------------------------------------
template <int K, int Cin, int Cout, int GT>
__global__ void __launch_bounds__(256)
conv_kernel(const float* __restrict__ in, int ldin,
            const int* __restrict__ nbr,        // [K][M]
            const float* __restrict__ W,        // [K][Cin][Cout]
            float* __restrict__ out, int ldout, int outOff,
            int M, int P) {
    constexpr int G = (K + GT - 1) / GT;
    constexpr int RPWI = 16;          // rows per warp per chunk
    constexpr int CH = 8 * RPWI;      // rows per chunk (8 warps)
    constexpr int RPB = 512;          // rows per block

    extern __shared__ float smem[];
    float* W_s = smem;                         // GT * Cin * Cout
    float* x_s = smem + GT * Cin * Cout;       // 8 * Cin

    const int tid = threadIdx.x;
    const int lane = tid & 31;
    const int w = tid >> 5;

    const float sc0 = g_scale[lane];
    const float sh0 = g_shift[lane];
    float sc1 = 0.f, sh1 = 0.f;
    if (Cin == 64) { sc1 = g_scale[lane + 32]; sh1 = g_shift[lane + 32]; }

    float* xr = x_s + w * Cin;

    const int blockStart = blockIdx.x * RPB;
    const int blockEnd = min(M, blockStart + RPB);
    int loaded = -1;

    for (int cs = blockStart; cs < blockEnd; cs += CH) {
        const int rowBase = cs + w * RPWI;
        float2 acc2[RPWI];
        float acc1[RPWI];
#pragma unroll
        for (int i = 0; i < RPWI; i++) { acc2[i] = make_float2(0.f, 0.f); acc1[i] = 0.f; }

        for (int g = 0; g < G; g++) {
            if (g != loaded) {
                __syncthreads();
                const int tg = min(GT, K - g * GT);
                const int total = tg * Cin * Cout;
                const float* Wg = W + (size_t)g * GT * Cin * Cout;
                for (int i = tid; i < total; i += 256) W_s[i] = Wg[i];
                __syncthreads();
                loaded = g;
            }
            const int tg = min(GT, K - g * GT);

#pragma unroll
            for (int i = 0; i < RPWI; i++) {
                const int r = rowBase + i;
                if (r >= blockEnd) continue;
                int idxl = P;
                if (lane < tg) idxl = nbr[(size_t)(g * GT + lane) * M + r];
                unsigned mask = __ballot_sync(0xffffffffu, idxl < P);
                while (mask) {
                    const int t = __ffs(mask) - 1;
                    mask &= mask - 1;
                    const int idx = __shfl_sync(0xffffffffu, idxl, t);
                    // gather + BN + ReLU into per-warp row buffer
                    float v0 = in[(size_t)idx * ldin + lane];
                    xr[lane] = fmaxf(fmaf(v0, sc0, sh0), 0.f);
                    if (Cin == 64) {
                        float v1 = in[(size_t)idx * ldin + 32 + lane];
                        xr[lane + 32] = fmaxf(fmaf(v1, sc1, sh1), 0.f);
                    }
                    __syncwarp();
                    const float* Wt = W_s + t * Cin * Cout;
                    const float4* x4 = (const float4*)xr;
                    if (Cout == 64) {
                        const float2* w2 = (const float2*)Wt + lane;   // [ci][2*lane]
                        float2 a = acc2[i];
#pragma unroll
                        for (int c4 = 0; c4 < Cin / 4; c4++) {
                            float4 xq = x4[c4];
                            float2 wv;
                            wv = w2[(4 * c4 + 0) * 32]; a.x = fmaf(xq.x, wv.x, a.x); a.y = fmaf(xq.x, wv.y, a.y);
                            wv = w2[(4 * c4 + 1) * 32]; a.x = fmaf(xq.y, wv.x, a.x); a.y = fmaf(xq.y, wv.y, a.y);
                            wv = w2[(4 * c4 + 2) * 32]; a.x = fmaf(xq.z, wv.x, a.x); a.y = fmaf(xq.z, wv.y, a.y);
                            wv = w2[(4 * c4 + 3) * 32]; a.x = fmaf(xq.w, wv.x, a.x); a.y = fmaf(xq.w, wv.y, a.y);
                        }
                        acc2[i] = a;
                    } else {
                        float a = acc1[i];
#pragma unroll
                        for (int c4 = 0; c4 < Cin / 4; c4++) {
                            float4 xq = x4[c4];
                            a = fmaf(xq.x, Wt[(4 * c4 + 0) * 32 + lane], a);
                            a = fmaf(xq.y, Wt[(4 * c4 + 1) * 32 + lane], a);
                            a = fmaf(xq.z, Wt[(4 * c4 + 2) * 32 + lane], a);
                            a = fmaf(xq.w, Wt[(4 * c4 + 3) * 32 + lane], a);
                        }
                        acc1[i] = a;
                    }
                    __syncwarp();
                }
            }
        }

#pragma unroll
        for (int i = 0; i < RPWI; i++) {
            const int r = rowBase + i;
            if (r >= blockEnd) continue;
            if (Cout == 64) {
                ((float2*)(out + (size_t)r * ldout + outOff))[lane] = acc2[i];
            } else {
                out[(size_t)r * ldout + outOff + lane] = acc1[i];
            }
        }
    }
}

// ---------------------------------------------------------------------------
// Stride-2 transpose conv (upsample): each fine voxel reads its unique coarse
// parent with a single kernel tap. All 8 taps (64 KB) live in smem.
// Writes into g_cat[:, 32:64].
// ---------------------------------------------------------------------------
__global__ void __launch_bounds__(256)
deconv_kernel(const float* __restrict__ in,          // [M][64]
              const int* __restrict__ up_cidx,       // [N]
              const int* __restrict__ up_k,          // [N]
              const float* __restrict__ W,           // [8][64][32]
              float* __restrict__ out,               // g_cat, ld 64, off 32
              int n) {
    extern __shared__ float smem[];
    float* W_s = smem;                 // 8*64*32
    float* x_s = smem + 8 * 64 * 32;   // 8*64
    for (int i = threadIdx.x; i < 8 * 64 * 32; i += blockDim.x) W_s[i] = W[i];
    __syncthreads();

    const int lane = threadIdx.x & 31;
    const int w = threadIdx.x >> 5;
    const float sc0 = g_scale[lane], sh0 = g_shift[lane];
    const float sc1 = g_scale[lane + 32], sh1 = g_shift[lane + 32];
    float* xr = x_s + w * 64;

    const int gw = blockIdx.x * 8 + w;
    const int stride = gridDim.x * 8;
    for (int r = gw; r < n; r += stride) {
        const int c = up_cidx[r];
        const int k = up_k[r];
        float v0 = in[(size_t)c * 64 + lane];
        float v1 = in[(size_t)c * 64 + 32 + lane];
        xr[lane] = fmaxf(fmaf(v0, sc0, sh0), 0.f);
        xr[lane + 32] = fmaxf(fmaf(v1, sc1, sh1), 0.f);
        __syncwarp();
        const float* Wt = W_s + k * 2048;
        const float4* x4 = (const float4*)xr;
        float acc = 0.f;
#pragma unroll
        for (int c4 = 0; c4 < 16; c4++) {
            float4 xq = x4[c4];
            acc = fmaf(xq.x, Wt[(4 * c4 + 0) * 32 + lane], acc);
            acc = fmaf(xq.y, Wt[(4 * c4 + 1) * 32 + lane], acc);
            acc = fmaf(xq.z, Wt[(4 * c4 + 2) * 32 + lane], acc);
            acc = fmaf(xq.w, Wt[(4 * c4 + 3) * 32 + lane], acc);
        }
        __syncwarp();
        out[(size_t)r * 64 + 32 + lane] = acc;
    }
}

// ---------------------------------------------------------------------------
extern "C" void kernel_launch(void* const* d_in, const int* in_sizes, int n_in,
                              void* d_out, int out_size) {
    (void)n_in; (void)out_size;
    const float* feat    = (const float*)d_in[0];
    const float* w_sub1  = (const float*)d_in[1];
    const float* w_down  = (const float*)d_in[2];
    const float* w_sub2  = (const float*)d_in[3];
    const float* w_up    = (const float*)d_in[4];
    const float* w_sub3  = (const float*)d_in[5];
    const float* g1 = (const float*)d_in[6],  *b1 = (const float*)d_in[7];
    const float* g2 = (const float*)d_in[8],  *b2 = (const float*)d_in[9];
    const float* g3 = (const float*)d_in[10], *b3 = (const float*)d_in[11];
    const float* g4 = (const float*)d_in[12], *b4 = (const float*)d_in[13];
    const float* g5 = (const float*)d_in[14], *b5 = (const float*)d_in[15];
    const int* nbr_fine   = (const int*)d_in[16];
    const int* nbr_coarse = (const int*)d_in[17];
    const int* down_idx   = (const int*)d_in[18];
    const int* up_cidx    = (const int*)d_in[19];
    const int* up_k       = (const int*)d_in[20];

    const int N = in_sizes[0] / 32;
    const int M = in_sizes[17] / 27;

    void* p;
    cudaGetSymbolAddress(&p, g_cat); float* cat = (float*)p;
    cudaGetSymbolAddress(&p, g_c1);  float* c1  = (float*)p;
    cudaGetSymbolAddress(&p, g_c2);  float* c2  = (float*)p;

    // smem budgets (group weights + 8 per-warp row buffers)
    const int SM1 = 27 * 32 * 32 * 4 + 8 * 32 * 4;   // 111616
    const int SMD = 8 * 32 * 64 * 4 + 8 * 32 * 4;    // 66560
    const int SM2 = 9 * 64 * 64 * 4 + 8 * 64 * 4;    // 149504
    const int SM3 = 27 * 64 * 32 * 4 + 8 * 64 * 4;   // 223232
    const int SMU = 8 * 64 * 32 * 4 + 8 * 64 * 4;    // 67584

    cudaFuncSetAttribute(conv_kernel<27, 32, 32, 27>, cudaFuncAttributeMaxDynamicSharedMemorySize, SM1);
    cudaFuncSetAttribute(conv_kernel<8, 32, 64, 8>,   cudaFuncAttributeMaxDynamicSharedMemorySize, SMD);
    cudaFuncSetAttribute(conv_kernel<27, 64, 64, 9>,  cudaFuncAttributeMaxDynamicSharedMemorySize, SM2);
    cudaFuncSetAttribute(conv_kernel<27, 64, 32, 27>, cudaFuncAttributeMaxDynamicSharedMemorySize, SM3);
    cudaFuncSetAttribute(deconv_kernel,               cudaFuncAttributeMaxDynamicSharedMemorySize, SMU);

    const int gridN = (N + 511) / 512;
    const int gridM = (M + 511) / 512;

    // BN1 -> sub1 (skip) into g_cat[:, 0:32]
    stats_partial<<<STATS_BLOCKS, 256>>>(feat, N, 32, 32);
    stats_final<<<1, 64>>>(N, 32, g1, b1);
    conv_kernel<27, 32, 32, 27><<<gridN, 256, SM1>>>(feat, 32, nbr_fine, w_sub1, cat, 64, 0, N, N);

    // BN2 -> down conv (32->64) at coarse level
    stats_partial<<<STATS_BLOCKS, 256>>>(cat, N, 32, 64);
    stats_final<<<1, 64>>>(N, 32, g2, b2);
    conv_kernel<8, 32, 64, 8><<<gridM, 256, SMD>>>(cat, 64, down_idx, w_down, c1, 64, 0, M, N);

    // BN3 -> coarse submanifold conv (64->64)
    stats_partial<<<STATS_BLOCKS, 256>>>(c1, M, 64, 64);
    stats_final<<<1, 64>>>(M, 64, g3, b3);
    conv_kernel<27, 64, 64, 9><<<gridM, 256, SM2>>>(c1, 64, nbr_coarse, w_sub2, c2, 64, 0, M, M);

    // BN4 -> deconv (64->32) into g_cat[:, 32:64]
    stats_partial<<<STATS_BLOCKS, 256>>>(c2, M, 64, 64);
    stats_final<<<1, 64>>>(M, 64, g4, b4);
    deconv_kernel<<<1024, 256, SMU>>>(c2, up_cidx, up_k, w_up, cat, N);

    // BN5 over concat -> final submanifold conv (64->32) directly to d_out
    stats_partial<<<STATS_BLOCKS, 256>>>(cat, N, 64, 64);
    stats_final<<<1, 64>>>(N, 64, g5, b5);
    conv_kernel<27, 64, 32, 27><<<gridN, 256, SM3>>>(cat, 64, nbr_fine, w_sub3,
                                                     (float*)d_out, 32, 0, N, N);
}

// round 3
// speedup vs baseline: 1.5024x; 1.5024x over previous
#include <cuda_runtime.h>

#define NMAX 200704
#define SB 1024   // stats partial blocks

__device__ float g_part[SB * 128];
__device__ float g_scale[64];
__device__ float g_shift[64];
__device__ float g_cat[(size_t)NMAX * 64];   // [N][64]: skip || upsampled
__device__ float g_c1[(size_t)NMAX * 64];    // [M][64]
__device__ float g_c2[(size_t)NMAX * 64];    // [M][64]

// ---------------------------------------------------------------------------
// Batch stats: float4 lanes, deterministic two-stage reduction.
// ---------------------------------------------------------------------------
__global__ void __launch_bounds__(256)
stats4(const float* __restrict__ x, int n, int C, int ld) {
    __shared__ float4 sm[512];
    const int tid = threadIdx.x;
    const int V = C / 4;            // float4 per row (8 or 16)
    const int rpi = 256 / V;        // rows per block per iter
    const int c4 = tid % V;
    const int rg = tid / V;
    float4 s = {0.f, 0.f, 0.f, 0.f}, q = {0.f, 0.f, 0.f, 0.f};
    for (int r = blockIdx.x * rpi + rg; r < n; r += gridDim.x * rpi) {
        float4 v = *(const float4*)(x + (size_t)r * ld + 4 * c4);
        s.x += v.x; s.y += v.y; s.z += v.z; s.w += v.w;
        q.x += v.x * v.x; q.y += v.y * v.y; q.z += v.z * v.z; q.w += v.w * v.w;
    }
    sm[tid] = s;
    sm[256 + tid] = q;
    __syncthreads();
    if (rg == 0) {
        float4 ts = {0.f, 0.f, 0.f, 0.f}, tq = {0.f, 0.f, 0.f, 0.f};
        for (int j = 0; j < rpi; j++) {
            float4 a = sm[j * V + c4];
            ts.x += a.x; ts.y += a.y; ts.z += a.z; ts.w += a.w;
            float4 b = sm[256 + j * V + c4];
            tq.x += b.x; tq.y += b.y; tq.z += b.z; tq.w += b.w;
        }
        float* p = g_part + blockIdx.x * 128 + 4 * c4;
        p[0] = ts.x; p[1] = ts.y; p[2] = ts.z; p[3] = ts.w;
        p[64] = tq.x; p[65] = tq.y; p[66] = tq.z; p[67] = tq.w;
    }
}

__global__ void stats_final(int n, int C, const float* __restrict__ gg, const float* __restrict__ bb) {
    int c = threadIdx.x;
    if (c >= C) return;
    float s0 = 0.f, s1 = 0.f, s2 = 0.f, s3 = 0.f;
    float q0 = 0.f, q1 = 0.f, q2 = 0.f, q3 = 0.f;
    for (int b = 0; b < SB; b += 4) {
        s0 += g_part[(b + 0) * 128 + c];      q0 += g_part[(b + 0) * 128 + 64 + c];
        s1 += g_part[(b + 1) * 128 + c];      q1 += g_part[(b + 1) * 128 + 64 + c];
        s2 += g_part[(b + 2) * 128 + c];      q2 += g_part[(b + 2) * 128 + 64 + c];
        s3 += g_part[(b + 3) * 128 + c];      q3 += g_part[(b + 3) * 128 + 64 + c];
    }
    float s = (s0 + s1) + (s2 + s3);
    float q = (q0 + q1) + (q2 + q3);
    float inv_n = 1.f / (float)n;
    float mu = s * inv_n;
    float var = q * inv_n - mu * mu;
    float sc = gg[c] * rsqrtf(var + 1e-4f);
    g_scale[c] = sc;
    g_shift[c] = bb[c] - mu * sc;
}

// ---------------------------------------------------------------------------
// Tap-major, weight-stationary sparse conv.
//   k loop outermost; each warp holds W[k][ci][co=lane(+half*32)] in registers.
//   x gathered coalesced (lane = ci), BN+ReLU, broadcast via shfl.
//   Output accumulated by deterministic RMW: block owns a contiguous row range,
//   a fixed warp owns each row stripe across all k -> ordered accumulation.
//   Prefetch of the next valid pair's gather hides L2 latency.
// ---------------------------------------------------------------------------
template <int K, int Cin, int Cout>
__global__ void __launch_bounds__(512, 1)
tapconv(const float* __restrict__ in, int ldin, int inOff,
        const int* __restrict__ nbr,          // [K][M]
        const float* __restrict__ W,          // [K][Cin][Cout]
        float* __restrict__ out, int ldout, int outOff,
        int M, int P) {
    const int tid = threadIdx.x;
    const int lane = tid & 31;
    const int w = tid >> 5;
    constexpr int HW = Cout / 32;     // half-warps per row stripe (1 or 2)
    constexpr int NWP = 16 / HW;      // row stripes per block
    const int wp = w / HW;
    const int half = w % HW;
    const int coB = half * 32;

    const int range = (M + gridDim.x - 1) / gridDim.x;
    const int b0 = blockIdx.x * range;
    const int b1 = min(M, b0 + range);

    // zero-init owned out region (poisoned / garbage before)
    for (int i = tid; i < (b1 - b0) * Cout; i += 512) {
        int r = b0 + i / Cout, c = i % Cout;
        out[(size_t)r * ldout + outOff + c] = 0.f;
    }
    __syncthreads();
    if (b0 >= b1) return;

    const float sc0 = g_scale[lane], sh0 = g_shift[lane];
    float sc1 = 0.f, sh1 = 0.f;
    if (Cin == 64) { sc1 = g_scale[lane + 32]; sh1 = g_shift[lane + 32]; }

    for (int k = 0; k < K; k++) {
        float wreg[Cin];
        const float* Wk = W + (size_t)k * Cin * Cout;
#pragma unroll
        for (int ci = 0; ci < Cin; ci++) wreg[ci] = Wk[ci * Cout + coB + lane];
        const int* nk = nbr + (size_t)k * M;

        for (int rb = b0 + wp * 32; rb < b1; rb += NWP * 32) {
            const int r_l = rb + lane;
            int idxl = (r_l < b1) ? nk[r_l] : P;
            unsigned mask = __ballot_sync(0xffffffffu, idxl < P);
            if (!mask) continue;
            int t = __ffs(mask) - 1;
            int idx = __shfl_sync(0xffffffffu, idxl, t);
            float v0 = in[(size_t)idx * ldin + inOff + lane];
            float v1 = (Cin == 64) ? in[(size_t)idx * ldin + inOff + 32 + lane] : 0.f;
            while (true) {
                mask &= mask - 1;
                int tn = 0; float p0 = 0.f, p1 = 0.f;
                if (mask) {                      // prefetch next pair
                    tn = __ffs(mask) - 1;
                    int idxn = __shfl_sync(0xffffffffu, idxl, tn);
                    p0 = in[(size_t)idxn * ldin + inOff + lane];
                    if (Cin == 64) p1 = in[(size_t)idxn * ldin + inOff + 32 + lane];
                }
                float x0 = fmaxf(fmaf(v0, sc0, sh0), 0.f);
                float x1 = (Cin == 64) ? fmaxf(fmaf(v1, sc1, sh1), 0.f) : 0.f;
                float a0 = 0.f, a1 = 0.f, a2 = 0.f, a3 = 0.f;
#pragma unroll
                for (int ci = 0; ci < Cin; ci += 4) {
                    float xa = __shfl_sync(0xffffffffu, (ci + 0 < 32) ? x0 : x1, (ci + 0) & 31);
                    float xb = __shfl_sync(0xffffffffu, (ci + 1 < 32) ? x0 : x1, (ci + 1) & 31);
                    float xc = __shfl_sync(0xffffffffu, (ci + 2 < 32) ? x0 : x1, (ci + 2) & 31);
                    float xd = __shfl_sync(0xffffffffu, (ci + 3 < 32) ? x0 : x1, (ci + 3) & 31);
                    a0 = fmaf(xa, wreg[ci + 0], a0);
                    a1 = fmaf(xb, wreg[ci + 1], a1);
                    a2 = fmaf(xc, wreg[ci + 2], a2);
                    a3 = fmaf(xd, wreg[ci + 3], a3);
                }
                const int r = rb + t;
                float* po = out + (size_t)r * ldout + outOff + coB + lane;
                *po += (a0 + a1) + (a2 + a3);
                if (!mask) break;
                t = tn; v0 = p0; v1 = p1;
            }
        }
    }
}

// ---------------------------------------------------------------------------
// Deconv (upsample, 1 tap per fine voxel): weights in smem (64KB -> 3 blk/SM),
// x via shfl, 4-way accumulator ILP.
// ---------------------------------------------------------------------------
__global__ void __launch_bounds__(512)
deconv2(const float* __restrict__ in,          // [M][64]
        const int* __restrict__ up_cidx,       // [N]
        const int* __restrict__ up_k,          // [N]
        const float* __restrict__ W,           // [8][64][32]
        float* __restrict__ out,               // g_cat, cols 32:64
        int n) {
    extern __shared__ float Ws[];              // 8*64*32
    for (int i = threadIdx.x; i < 8 * 2048; i += 512) Ws[i] = W[i];
    __syncthreads();

    const int lane = threadIdx.x & 31;
    const int w = threadIdx.x >> 5;
    const float sc0 = g_scale[lane], sh0 = g_shift[lane];
    const float sc1 = g_scale[lane + 32], sh1 = g_shift[lane + 32];

    const int gw = blockIdx.x * 16 + w;
    const int stride = gridDim.x * 16;
    for (int r = gw; r < n; r += stride) {
        const int c = up_cidx[r];
        const int k = up_k[r];
        float v0 = in[(size_t)c * 64 + lane];
        float v1 = in[(size_t)c * 64 + 32 + lane];
        float x0 = fmaxf(fmaf(v0, sc0, sh0), 0.f);
        float x1 = fmaxf(fmaf(v1, sc1, sh1), 0.f);
        const float* Wt = Ws + k * 2048;
        float a0 = 0.f, a1 = 0.f, a2 = 0.f, a3 = 0.f;
#pragma unroll
        for (int ci = 0; ci < 64; ci += 4) {
            float xa = __shfl_sync(0xffffffffu, (ci + 0 < 32) ? x0 : x1, (ci + 0) & 31);
            float xb = __shfl_sync(0xffffffffu, (ci + 1 < 32) ? x0 : x1, (ci + 1) & 31);
            float xc = __shfl_sync(0xffffffffu, (ci + 2 < 32) ? x0 : x1, (ci + 2) & 31);
            float xd = __shfl_sync(0xffffffffu, (ci + 3 < 32) ? x0 : x1, (ci + 3) & 31);
            a0 = fmaf(xa, Wt[(ci + 0) * 32 + lane], a0);
            a1 = fmaf(xb, Wt[(ci + 1) * 32 + lane], a1);
            a2 = fmaf(xc, Wt[(ci + 2) * 32 + lane], a2);
            a3 = fmaf(xd, Wt[(ci + 3) * 32 + lane], a3);
        }
        out[(size_t)r * 64 + 32 + lane] = (a0 + a1) + (a2 + a3);
    }
}

// ---------------------------------------------------------------------------
extern "C" void kernel_launch(void* const* d_in, const int* in_sizes, int n_in,
                              void* d_out, int out_size) {
    (void)n_in; (void)out_size;
    const float* feat    = (const float*)d_in[0];
    const float* w_sub1  = (const float*)d_in[1];
    const float* w_down  = (const float*)d_in[2];
    const float* w_sub2  = (const float*)d_in[3];
    const float* w_up    = (const float*)d_in[4];
    const float* w_sub3  = (const float*)d_in[5];
    const float* g1 = (const float*)d_in[6],  *b1 = (const float*)d_in[7];
    const float* g2 = (const float*)d_in[8],  *b2 = (const float*)d_in[9];
    const float* g3 = (const float*)d_in[10], *b3 = (const float*)d_in[11];
    const float* g4 = (const float*)d_in[12], *b4 = (const float*)d_in[13];
    const float* g5 = (const float*)d_in[14], *b5 = (const float*)d_in[15];
    const int* nbr_fine   = (const int*)d_in[16];
    const int* nbr_coarse = (const int*)d_in[17];
    const int* down_idx   = (const int*)d_in[18];
    const int* up_cidx    = (const int*)d_in[19];
    const int* up_k       = (const int*)d_in[20];

    const int N = in_sizes[0] / 32;
    const int M = in_sizes[17] / 27;

    void* p;
    cudaGetSymbolAddress(&p, g_cat); float* cat = (float*)p;
    cudaGetSymbolAddress(&p, g_c1);  float* c1  = (float*)p;
    cudaGetSymbolAddress(&p, g_c2);  float* c2  = (float*)p;

    const int SMU = 8 * 64 * 32 * 4;   // 64KB
    cudaFuncSetAttribute(deconv2, cudaFuncAttributeMaxDynamicSharedMemorySize, SMU);

    const int GRID = 296;   // 2 blocks/SM where regs allow, 2 waves otherwise

    // BN1 -> sub1 (skip) into g_cat[:, 0:32]
    stats4<<<SB, 256>>>(feat, N, 32, 32);
    stats_final<<<1, 64>>>(N, 32, g1, b1);
    tapconv<27, 32, 32><<<GRID, 512>>>(feat, 32, 0, nbr_fine, w_sub1, cat, 64, 0, N, N);

    // BN2 -> down conv (32->64)
    stats4<<<SB, 256>>>(cat, N, 32, 64);
    stats_final<<<1, 64>>>(N, 32, g2, b2);
    tapconv<8, 32, 64><<<GRID, 512>>>(cat, 64, 0, down_idx, w_down, c1, 64, 0, M, N);

    // BN3 -> coarse submanifold conv (64->64)
    stats4<<<SB, 256>>>(c1, M, 64, 64);
    stats_final<<<1, 64>>>(M, 64, g3, b3);
    tapconv<27, 64, 64><<<GRID, 512>>>(c1, 64, 0, nbr_coarse, w_sub2, c2, 64, 0, M, M);

    // BN4 -> deconv (64->32) into g_cat[:, 32:64]
    stats4<<<SB, 256>>>(c2, M, 64, 64);
    stats_final<<<1, 64>>>(M, 64, g4, b4);
    deconv2<<<444, 512, SMU>>>(c2, up_cidx, up_k, w_up, cat, N);

    // BN5 over concat -> final conv (64->32) to d_out
    stats4<<<SB, 256>>>(cat, N, 64, 64);
    stats_final<<<1, 64>>>(N, 64, g5, b5);
    tapconv<27, 64, 32><<<GRID, 512>>>(cat, 64, 0, nbr_fine, w_sub3,
                                       (float*)d_out, 32, 0, N, N);
}